// round 3
// baseline (speedup 1.0000x reference)
#include <cuda_runtime.h>
#include <cstddef>

// Problem constants (fixed by reference)
#define N_KC   200
#define N_MBON 20
#define N_FBN  60
#define N_DAN  20
#define N_REC  100
#define N_EXT  2
#define T_TOT  61
#define T_STEPS 60
#define KPT    7          // k = lane + 32*i, valid k < 200
#define NTHREADS 320
#define WM_CHUNK 34       // Wm cols per thread-group (3 groups of 100 threads)

// Masked, transposed recurrent weights: g_WmT[i][j] = Wm[j][i], rows 100..101 zero.
// Batch-invariant -> device global, written by prep kernel each launch.
__device__ float g_WmT[102 * 100];

__global__ void prep_wm_kernel(const float* __restrict__ W_recur) {
    int i = blockIdx.x * blockDim.x + threadIdx.x;
    if (i < 102 * 100) {
        int r = i / 100;   // source column index (0..101)
        int c = i % 100;   // source row index j
        float v = 0.0f;
        if (r < 100) {
            v = W_recur[c * 100 + r];
            if (c < N_MBON && r >= N_REC - N_DAN) v = 0.0f;  // Wm mask
        }
        g_WmT[i] = v;
    }
}

// smem layout (floats)
#define OFF_RK   0        // 12200 : r_kc slab [k*61 + t]
#define OFF_R    12200    // 104   : current r, zero-padded to 104
#define OFF_I    12304    // 100   : I_tot
#define OFF_WRP  12404    // 300   : Wr partials
#define OFF_RBK  12704    // 400   : rbk double buffer (2 x 200)
#define OFF_RBD  13104    // 20
#define OFF_BIAS 13124    // 100
#define OFF_WRO  13224    // 20
#define OFF_WEXT 13244    // 120
#define OFF_REXT 13364    // 122
#define SM_FLOATS 13486

__global__ __launch_bounds__(NTHREADS, 3)
void cond_rnn_kernel(const float* __restrict__ r_kc,
                     const float* __restrict__ r_ext,
                     const float* __restrict__ timev,
                     const float* __restrict__ W0,
                     const float* __restrict__ wt0,
                     const float* __restrict__ W_ext,
                     const float* __restrict__ W_readout,
                     const float* __restrict__ bias,
                     float* __restrict__ out,
                     int B)
{
    extern __shared__ float sm[];
    float* s_rk   = sm + OFF_RK;
    float* s_r    = sm + OFF_R;
    float* s_I    = sm + OFF_I;
    float* s_wrp  = sm + OFF_WRP;
    float* s_rbk  = sm + OFF_RBK;   // two buffers of 200
    float* s_rbd  = sm + OFF_RBD;
    float* s_bias = sm + OFF_BIAS;
    float* s_wro  = sm + OFF_WRO;
    float* s_wext = sm + OFF_WEXT;
    float* s_rext = sm + OFF_REXT;

    const int b    = blockIdx.x;
    const int tid  = threadIdx.x;
    const int w    = tid >> 5;     // warp id 0..9
    const int lane = tid & 31;

    const float dt = timev[1] - timev[0];
    const float cW = dt * (1.0f / 5.0f);  // dt / TAU_W
    const float cR = dt;                  // dt / TAU_R

    // output section offsets
    const size_t WF   = (size_t)T_TOT * B * N_REC;
    const size_t WTF  = WF + (size_t)B * (N_MBON * N_KC);
    const size_t RO   = WTF + (size_t)B * (N_MBON * N_KC);

    // ---- stage r_kc[b] slab into smem (coalesced float4) ----
    const float* rkb = r_kc + (size_t)b * (N_KC * T_TOT);
    {
        const float4* src = (const float4*)rkb;
        float4* dst = (float4*)s_rk;
        for (int i = tid; i < (N_KC * T_TOT) / 4; i += NTHREADS) dst[i] = src[i];
    }

    // ---- init small shared state ----
    if (tid < 100) {
        s_bias[tid] = bias[tid];
        float r0 = (tid < N_MBON) ? 0.0f : 0.1f;
        s_r[tid] = r0;
        s_I[tid] = 0.0f;                            // DAN slice stays 0 forever
        out[(size_t)b * N_REC + tid] = r0;          // r_all[0]
    }
    if (tid >= 100 && tid < 104) s_r[tid] = 0.0f;   // zero pad (Wr reads to 101)
    if (tid < 20) { s_wro[tid] = W_readout[tid]; s_rbd[tid] = 0.1f; }
    if (tid < 120) s_wext[tid] = W_ext[tid];
    if (tid < 200) s_rbk[tid] = rkb[tid * T_TOT];   // rbk0 into buffer 0
    if (tid < 122) s_rext[tid] = r_ext[(size_t)b * (N_EXT * T_TOT) + tid];
    if (tid == 0)  out[RO + b] = 0.0f;              // readout0 (MBON r is 0)

    // ---- plastic weights W / wt in registers: warp w owns rows (w, w+10) ----
    const int m1 = w;
    const int m2 = w + 10;
    float Wa[KPT], Wb_[KPT], wta[KPT], wtb[KPT];
    {
        const float* Wg  = W0  + (size_t)b * (N_MBON * N_KC);
        const float* wtg = wt0 + (size_t)b * (N_MBON * N_KC);
        #pragma unroll
        for (int i = 0; i < KPT; i++) {
            int k = lane + 32 * i;
            bool ok = (k < N_KC);
            Wa[i]  = ok ? Wg [m1 * N_KC + k] : 0.0f;
            Wb_[i] = ok ? Wg [m2 * N_KC + k] : 0.0f;
            wta[i] = ok ? wtg[m1 * N_KC + k] : 0.0f;
            wtb[i] = ok ? wtg[m2 * N_KC + k] : 0.0f;
        }
    }

    // Wr-group coordinates (threads 0..299): row jj, col chunk [i0, i0+34)
    const int jj = (tid < 300) ? (tid % 100) : 0;
    const int i0 = (tid < 300) ? (tid / 100) * WM_CHUNK : 0;
    const float* wcol = g_WmT + i0 * 100 + jj;

    __syncthreads();

    float* out_r = out + (size_t)B * N_REC + (size_t)b * N_REC;  // r_all[1]
    float* out_ro = out + RO + B + b;                            // readout[1]
    const size_t rstride = (size_t)B * N_REC;

    for (int t = 0; t < T_STEPS; t++) {
        const int cur = t & 1;
        const int nxt = cur ^ 1;

        // ================= P0 =================
        // rk into regs + I_kc row dots (2 independent chains)
        float rk[KPT];
        #pragma unroll
        for (int i = 0; i < KPT; i++) {
            int k = lane + 32 * i;
            rk[i] = (k < N_KC) ? s_rk[k * T_TOT + t] : 0.0f;
        }
        float p1 = 0.0f, p2 = 0.0f;
        #pragma unroll
        for (int i = 0; i < KPT; i++) {
            p1 = fmaf(Wa[i],  rk[i], p1);
            p2 = fmaf(Wb_[i], rk[i], p2);
        }
        #pragma unroll
        for (int o = 16; o > 0; o >>= 1) {
            p1 += __shfl_xor_sync(0xFFFFFFFFu, p1, o);
            p2 += __shfl_xor_sync(0xFFFFFFFFu, p2, o);
        }
        if (lane == 0) { s_I[m1] = p1; s_I[m2] = p2; }

        // I_fbn
        if (tid < N_FBN) {
            float re0 = s_rext[t];
            float re1 = s_rext[T_TOT + t];
            s_I[N_MBON + tid] = fmaf(s_wext[tid * 2], re0, s_wext[tid * 2 + 1] * re1);
        }

        // Wr partials: Wm from global (L1/L2-resident table), r from smem.
        // Two accumulators to halve the FMA dependency chain.
        if (tid < 300) {
            float q0 = 0.0f, q1 = 0.0f;
            #pragma unroll
            for (int c = 0; c < WM_CHUNK; c += 2) {
                q0 = fmaf(__ldg(wcol + (c    ) * 100), s_r[i0 + c    ], q0);
                q1 = fmaf(__ldg(wcol + (c + 1) * 100), s_r[i0 + c + 1], q1);
            }
            s_wrp[tid] = q0 + q1;
        }

        // rbk update: read buf[cur], write buf[nxt]
        if (tid < N_KC) {
            float rbk = s_rbk[cur * 200 + tid];
            float rkt = s_rk[tid * T_TOT + t];
            s_rbk[nxt * 200 + tid] = fmaf(rkt - rbk, cW, rbk);
        }
        __syncthreads();

        // ================= P1 =================
        if (tid < N_REC) {
            float x = s_wrp[tid] + s_wrp[100 + tid] + s_wrp[200 + tid]
                    + s_bias[tid] + s_I[tid];
            float rold = s_r[tid];
            float rn = fmaf(fmaxf(x, 0.0f) - rold, cR, rold);
            s_r[tid] = rn;
            out_r[tid] = rn;
            if (tid >= N_REC - N_DAN) {
                int d = tid - (N_REC - N_DAN);
                float rbd = s_rbd[d];
                s_rbd[d] = fmaf(rn - rbd, cW, rbd);
            }
        }
        __syncthreads();

        // ================= P2 (no trailing barrier; rbk double-buffered) ====
        {
            float rbd1  = s_rbd[m1],     rbd2 = s_rbd[m2];
            float rdn1  = -s_r[80 + m1], rdn2 = -s_r[80 + m2];
            const float* rbk_new = s_rbk + nxt * 200;
            #pragma unroll
            for (int i = 0; i < KPT; i++) {
                int k = lane + 32 * i;
                if (k < N_KC) {
                    float rbk = rbk_new[k];
                    float dw1 = fmaf(rbd1, rk[i], rdn1 * rbk);
                    wta[i] = fmaf(dw1, dt, wta[i]);
                    Wa[i]  = fminf(fmaxf(fmaf(wta[i] - Wa[i], cW, Wa[i]), 0.0f), 0.05f);
                    float dw2 = fmaf(rbd2, rk[i], rdn2 * rbk);
                    wtb[i] = fmaf(dw2, dt, wtb[i]);
                    Wb_[i] = fminf(fmaxf(fmaf(wtb[i] - Wb_[i], cW, Wb_[i]), 0.0f), 0.05f);
                }
            }
        }

        // readout (warp 0; reads post-barrier s_r)
        if (w == 0) {
            float v = (lane < N_MBON) ? s_r[lane] * s_wro[lane] : 0.0f;
            #pragma unroll
            for (int o = 16; o > 0; o >>= 1)
                v += __shfl_xor_sync(0xFFFFFFFFu, v, o);
            if (lane == 0) *out_ro = v;
        }

        out_r  += rstride;
        out_ro += B;
        // no barrier: next P0 writes s_I/s_wrp (readers are 2 barriers back)
        // and rbk buf[cur] which nobody still reads.
    }

    // ---- final W / wt ----
    {
        float* Wf  = out + WF  + (size_t)b * (N_MBON * N_KC);
        float* wtf = out + WTF + (size_t)b * (N_MBON * N_KC);
        #pragma unroll
        for (int i = 0; i < KPT; i++) {
            int k = lane + 32 * i;
            if (k < N_KC) {
                Wf [m1 * N_KC + k] = Wa[i];
                Wf [m2 * N_KC + k] = Wb_[i];
                wtf[m1 * N_KC + k] = wta[i];
                wtf[m2 * N_KC + k] = wtb[i];
            }
        }
    }
}

extern "C" void kernel_launch(void* const* d_in, const int* in_sizes, int n_in,
                              void* d_out, int out_size) {
    const float* r_kc      = (const float*)d_in[0];
    const float* r_ext     = (const float*)d_in[1];
    const float* timev     = (const float*)d_in[2];
    const float* W0        = (const float*)d_in[3];
    const float* wt0       = (const float*)d_in[4];
    const float* W_recur   = (const float*)d_in[5];
    const float* W_ext     = (const float*)d_in[6];
    const float* W_readout = (const float*)d_in[7];
    const float* bias      = (const float*)d_in[8];
    float* out = (float*)d_out;

    int B = in_sizes[0] / (N_KC * T_TOT);

    static bool attr_set = false;
    if (!attr_set) {
        cudaFuncSetAttribute(cond_rnn_kernel,
                             cudaFuncAttributeMaxDynamicSharedMemorySize,
                             SM_FLOATS * sizeof(float));
        attr_set = true;
    }

    prep_wm_kernel<<<(102 * 100 + 255) / 256, 256>>>(W_recur);
    cond_rnn_kernel<<<B, NTHREADS, SM_FLOATS * sizeof(float)>>>(
        r_kc, r_ext, timev, W0, wt0, W_ext, W_readout, bias, out, B);
}

// round 4
// speedup vs baseline: 1.0148x; 1.0148x over previous
#include <cuda_runtime.h>
#include <cstddef>

// Problem constants (fixed by reference)
#define N_KC   200
#define N_MBON 20
#define N_FBN  60
#define N_DAN  20
#define N_REC  100
#define N_EXT  2
#define T_TOT  61
#define T_STEPS 60
#define NTHREADS 320
#define WM_CHUNK 36       // Wm cols per thread-group (9 float4s, zero-padded past 100)
#define WM_Q     9

// smem layout (floats) — all float4-aligned where needed
#define OFF_RK   0        // 12200 : r_kc slab transposed [t*200 + k]
#define OFF_R    12200    // 108   : current r, zero-padded to 108
#define OFF_I    12308    // 100   : I_tot
#define OFF_WRP  12408    // 300   : Wr partials
#define OFF_RBK  12708    // 400   : rbk double buffer (2 x 200)
#define OFF_RBD  13108    // 20
#define OFF_BIAS 13128    // 100
#define OFF_WRO  13228    // 20
#define OFF_WEXT 13248    // 120
#define OFF_REXT 13368    // 122
#define SM_FLOATS 13490

__global__ __launch_bounds__(NTHREADS, 2)
void cond_rnn_kernel(const float* __restrict__ r_kc,
                     const float* __restrict__ r_ext,
                     const float* __restrict__ timev,
                     const float* __restrict__ W0,
                     const float* __restrict__ wt0,
                     const float* __restrict__ W_recur,
                     const float* __restrict__ W_ext,
                     const float* __restrict__ W_readout,
                     const float* __restrict__ bias,
                     float* __restrict__ out,
                     int B)
{
    extern __shared__ float sm[];
    float* s_rk   = sm + OFF_RK;
    float* s_r    = sm + OFF_R;
    float* s_I    = sm + OFF_I;
    float* s_wrp  = sm + OFF_WRP;
    float* s_rbk  = sm + OFF_RBK;   // two buffers of 200
    float* s_rbd  = sm + OFF_RBD;
    float* s_bias = sm + OFF_BIAS;
    float* s_wro  = sm + OFF_WRO;
    float* s_wext = sm + OFF_WEXT;
    float* s_rext = sm + OFF_REXT;

    const int b    = blockIdx.x;
    const int tid  = threadIdx.x;
    const int w    = tid >> 5;     // warp id 0..9
    const int lane = tid & 31;

    const float dt = timev[1] - timev[0];
    const float cW = dt * (1.0f / 5.0f);  // dt / TAU_W
    const float cR = dt;                  // dt / TAU_R

    // output section offsets
    const size_t WF   = (size_t)T_TOT * B * N_REC;
    const size_t WTF  = WF + (size_t)B * (N_MBON * N_KC);
    const size_t RO   = WTF + (size_t)B * (N_MBON * N_KC);

    // ---- stage r_kc[b] slab into smem, TRANSPOSED to [t*200 + k] ----
    const float* rkb = r_kc + (size_t)b * (N_KC * T_TOT);
    for (int i = tid; i < N_KC * T_TOT; i += NTHREADS) {
        int k = i / T_TOT;
        int t = i - k * T_TOT;
        s_rk[t * N_KC + k] = rkb[i];
    }

    // ---- init small shared state ----
    if (tid < 100) {
        s_bias[tid] = bias[tid];
        float r0 = (tid < N_MBON) ? 0.0f : 0.1f;
        s_r[tid] = r0;
        s_I[tid] = 0.0f;                            // DAN slice stays 0 forever
        out[(size_t)b * N_REC + tid] = r0;          // r_all[0]
    }
    if (tid >= 100 && tid < 108) s_r[tid] = 0.0f;   // zero pad for float4 Wr reads
    if (tid < 20) { s_wro[tid] = W_readout[tid]; s_rbd[tid] = 0.1f; }
    if (tid < 120) s_wext[tid] = W_ext[tid];
    if (tid < 200) s_rbk[tid] = rkb[tid * T_TOT];   // rbk0 into buffer 0
    if (tid < 122) s_rext[tid] = r_ext[(size_t)b * (N_EXT * T_TOT) + tid];
    if (tid == 0)  out[RO + b] = 0.0f;              // readout0 (MBON r is 0)

    // ---- plastic weights W / wt in registers (float4 quads) ----
    // warp w owns rows (w, w+10); thread holds k in {4q..4q+3}, q = lane + 32*i, q < 50
    const int m1 = w;
    const int m2 = w + 10;
    const int q0i = lane;           // quad 0, always valid (lane < 50)
    const int q1i = 32 + lane;      // quad 1, valid if lane < 18
    const bool v1 = (lane < 18);

    float Wa[8], Wb_[8], wta[8], wtb[8];
    {
        const float* Wg  = W0  + (size_t)b * (N_MBON * N_KC);
        const float* wtg = wt0 + (size_t)b * (N_MBON * N_KC);
        *(float4*)(Wa)      = *(const float4*)(Wg  + m1 * N_KC + 4 * q0i);
        *(float4*)(Wb_)     = *(const float4*)(Wg  + m2 * N_KC + 4 * q0i);
        *(float4*)(wta)     = *(const float4*)(wtg + m1 * N_KC + 4 * q0i);
        *(float4*)(wtb)     = *(const float4*)(wtg + m2 * N_KC + 4 * q0i);
        float4 z = make_float4(0.f, 0.f, 0.f, 0.f);
        *(float4*)(Wa + 4)  = v1 ? *(const float4*)(Wg  + m1 * N_KC + 4 * q1i) : z;
        *(float4*)(Wb_ + 4) = v1 ? *(const float4*)(Wg  + m2 * N_KC + 4 * q1i) : z;
        *(float4*)(wta + 4) = v1 ? *(const float4*)(wtg + m1 * N_KC + 4 * q1i) : z;
        *(float4*)(wtb + 4) = v1 ? *(const float4*)(wtg + m2 * N_KC + 4 * q1i) : z;
    }

    // ---- W_recur (masked -> Wm) in registers: thread-group (jj, i0) ----
    float wm[WM_CHUNK];
    const int jj = (tid < 300) ? (tid % 100) : 0;
    const int i0 = (tid < 300) ? (tid / 100) * WM_CHUNK : 0;
    #pragma unroll
    for (int c = 0; c < WM_CHUNK; c++) {
        int ia = i0 + c;
        float v = 0.0f;
        if (tid < 300 && ia < N_REC) {
            v = W_recur[jj * N_REC + ia];
            if (jj < N_MBON && ia >= N_REC - N_DAN) v = 0.0f;  // Wm mask
        }
        wm[c] = v;
    }

    __syncthreads();

    float* out_r  = out + (size_t)B * N_REC + (size_t)b * N_REC;  // r_all[1]
    float* out_ro = out + RO + B + b;                              // readout[1]
    const size_t rstride = (size_t)B * N_REC;

    for (int t = 0; t < T_STEPS; t++) {
        const int cur = t & 1;
        const int nxt = cur ^ 1;
        const float* rkt_row = s_rk + t * N_KC;

        // ================= P0 =================
        // rk quads (2 x LDS.128) + I_kc row dots
        float rk[8];
        *(float4*)(rk) = *(const float4*)(rkt_row + 4 * q0i);
        *(float4*)(rk + 4) = v1 ? *(const float4*)(rkt_row + 4 * q1i)
                                : make_float4(0.f, 0.f, 0.f, 0.f);
        float p1a = 0.f, p1b = 0.f, p2a = 0.f, p2b = 0.f;
        #pragma unroll
        for (int j = 0; j < 8; j += 2) {
            p1a = fmaf(Wa[j],      rk[j],     p1a);
            p1b = fmaf(Wa[j + 1],  rk[j + 1], p1b);
            p2a = fmaf(Wb_[j],     rk[j],     p2a);
            p2b = fmaf(Wb_[j + 1], rk[j + 1], p2b);
        }
        float p1 = p1a + p1b, p2 = p2a + p2b;
        #pragma unroll
        for (int o = 16; o > 0; o >>= 1) {
            p1 += __shfl_xor_sync(0xFFFFFFFFu, p1, o);
            p2 += __shfl_xor_sync(0xFFFFFFFFu, p2, o);
        }
        if (lane == 0) { s_I[m1] = p1; s_I[m2] = p2; }

        // I_fbn
        if (tid < N_FBN) {
            float re0 = s_rext[t];
            float re1 = s_rext[T_TOT + t];
            float2 we = *(const float2*)(s_wext + tid * 2);
            s_I[N_MBON + tid] = fmaf(we.x, re0, we.y * re1);
        }

        // Wr partials: 9 broadcast LDS.128 + 36 FMA (2 accumulator chains)
        if (tid < 300) {
            float a0 = 0.f, a1 = 0.f;
            #pragma unroll
            for (int c = 0; c < WM_Q; c++) {
                float4 rv = *(const float4*)(s_r + i0 + 4 * c);
                a0 = fmaf(wm[4 * c],     rv.x, a0);
                a1 = fmaf(wm[4 * c + 1], rv.y, a1);
                a0 = fmaf(wm[4 * c + 2], rv.z, a0);
                a1 = fmaf(wm[4 * c + 3], rv.w, a1);
            }
            s_wrp[tid] = a0 + a1;
        }

        // rbk update: read buf[cur], write buf[nxt] (contiguous, coalesced)
        if (tid < N_KC) {
            float rbk = s_rbk[cur * 200 + tid];
            float rkt = rkt_row[tid];
            s_rbk[nxt * 200 + tid] = fmaf(rkt - rbk, cW, rbk);
        }
        __syncthreads();

        // ================= P1 =================
        if (tid < N_REC) {
            float x = s_wrp[tid] + s_wrp[100 + tid] + s_wrp[200 + tid]
                    + s_bias[tid] + s_I[tid];
            float rold = s_r[tid];
            float rn = fmaf(fmaxf(x, 0.0f) - rold, cR, rold);
            s_r[tid] = rn;
            out_r[tid] = rn;
            if (tid >= N_REC - N_DAN) {
                int d = tid - (N_REC - N_DAN);
                float rbd = s_rbd[d];
                s_rbd[d] = fmaf(rn - rbd, cW, rbd);
            }
        }
        __syncthreads();

        // ================= P2 (no trailing barrier; rbk double-buffered) ====
        {
            float rbd1 = s_rbd[m1],      rbd2 = s_rbd[m2];
            float rdn1 = -s_r[80 + m1],  rdn2 = -s_r[80 + m2];
            const float* rbk_new = s_rbk + nxt * 200;
            float rb[8];
            *(float4*)(rb) = *(const float4*)(rbk_new + 4 * q0i);
            *(float4*)(rb + 4) = v1 ? *(const float4*)(rbk_new + 4 * q1i)
                                    : make_float4(0.f, 0.f, 0.f, 0.f);
            #pragma unroll
            for (int j = 0; j < 8; j++) {
                float dw1 = fmaf(rbd1, rk[j], rdn1 * rb[j]);
                wta[j] = fmaf(dw1, dt, wta[j]);
                Wa[j]  = fminf(fmaxf(fmaf(wta[j] - Wa[j], cW, Wa[j]), 0.0f), 0.05f);
                float dw2 = fmaf(rbd2, rk[j], rdn2 * rb[j]);
                wtb[j] = fmaf(dw2, dt, wtb[j]);
                Wb_[j] = fminf(fmaxf(fmaf(wtb[j] - Wb_[j], cW, Wb_[j]), 0.0f), 0.05f);
            }
        }

        // readout (warp 0; reads post-barrier s_r)
        if (w == 0) {
            float v = (lane < N_MBON) ? s_r[lane] * s_wro[lane] : 0.0f;
            #pragma unroll
            for (int o = 16; o > 0; o >>= 1)
                v += __shfl_xor_sync(0xFFFFFFFFu, v, o);
            if (lane == 0) *out_ro = v;
        }

        out_r  += rstride;
        out_ro += B;
        // no barrier: next P0 writes s_I/s_wrp (their readers are 2 barriers
        // back) and rbk buf[cur] which nobody still reads.
    }

    // ---- final W / wt (float4 stores) ----
    {
        float* Wf  = out + WF  + (size_t)b * (N_MBON * N_KC);
        float* wtf = out + WTF + (size_t)b * (N_MBON * N_KC);
        *(float4*)(Wf  + m1 * N_KC + 4 * q0i) = *(const float4*)(Wa);
        *(float4*)(Wf  + m2 * N_KC + 4 * q0i) = *(const float4*)(Wb_);
        *(float4*)(wtf + m1 * N_KC + 4 * q0i) = *(const float4*)(wta);
        *(float4*)(wtf + m2 * N_KC + 4 * q0i) = *(const float4*)(wtb);
        if (v1) {
            *(float4*)(Wf  + m1 * N_KC + 4 * q1i) = *(const float4*)(Wa + 4);
            *(float4*)(Wf  + m2 * N_KC + 4 * q1i) = *(const float4*)(Wb_ + 4);
            *(float4*)(wtf + m1 * N_KC + 4 * q1i) = *(const float4*)(wta + 4);
            *(float4*)(wtf + m2 * N_KC + 4 * q1i) = *(const float4*)(wtb + 4);
        }
    }
}

extern "C" void kernel_launch(void* const* d_in, const int* in_sizes, int n_in,
                              void* d_out, int out_size) {
    const float* r_kc      = (const float*)d_in[0];
    const float* r_ext     = (const float*)d_in[1];
    const float* timev     = (const float*)d_in[2];
    const float* W0        = (const float*)d_in[3];
    const float* wt0       = (const float*)d_in[4];
    const float* W_recur   = (const float*)d_in[5];
    const float* W_ext     = (const float*)d_in[6];
    const float* W_readout = (const float*)d_in[7];
    const float* bias      = (const float*)d_in[8];
    float* out = (float*)d_out;

    int B = in_sizes[0] / (N_KC * T_TOT);

    static bool attr_set = false;
    if (!attr_set) {
        cudaFuncSetAttribute(cond_rnn_kernel,
                             cudaFuncAttributeMaxDynamicSharedMemorySize,
                             SM_FLOATS * sizeof(float));
        attr_set = true;
    }

    cond_rnn_kernel<<<B, NTHREADS, SM_FLOATS * sizeof(float)>>>(
        r_kc, r_ext, timev, W0, wt0, W_recur, W_ext, W_readout, bias, out, B);
}

// round 5
// speedup vs baseline: 1.0670x; 1.0515x over previous
#include <cuda_runtime.h>
#include <cstddef>

// Problem constants (fixed by reference)
#define N_KC   200
#define N_MBON 20
#define N_FBN  60
#define N_DAN  20
#define N_REC  100
#define N_EXT  2
#define T_TOT  61
#define T_STEPS 60
#define KPT    7          // k = lane + 32*i, valid k < 200
#define NTHREADS 640
#define WM_CHUNK 34       // Wm cols per thread-group (3 groups of 100 threads)

// smem layout (floats)
#define OFF_RK   0        // 12200 : r_kc slab [k*61 + t]
#define OFF_R    12200    // 104   : current r, zero-padded to 104
#define OFF_I    12304    // 100   : I_tot
#define OFF_WRP  12404    // 300   : Wr partials
#define OFF_RBK  12704    // 400   : rbk double buffer (2 x 200)
#define OFF_RBD  13104    // 20
#define OFF_BIAS 13124    // 100
#define OFF_WRO  13224    // 20
#define OFF_WEXT 13244    // 120
#define OFF_REXT 13364    // 122
#define SM_FLOATS 13486

__global__ __launch_bounds__(NTHREADS, 2)
void cond_rnn_kernel(const float* __restrict__ r_kc,
                     const float* __restrict__ r_ext,
                     const float* __restrict__ timev,
                     const float* __restrict__ W0,
                     const float* __restrict__ wt0,
                     const float* __restrict__ W_recur,
                     const float* __restrict__ W_ext,
                     const float* __restrict__ W_readout,
                     const float* __restrict__ bias,
                     float* __restrict__ out,
                     int B)
{
    extern __shared__ float sm[];
    float* s_rk   = sm + OFF_RK;
    float* s_r    = sm + OFF_R;
    float* s_I    = sm + OFF_I;
    float* s_wrp  = sm + OFF_WRP;
    float* s_rbk  = sm + OFF_RBK;   // two buffers of 200
    float* s_rbd  = sm + OFF_RBD;
    float* s_bias = sm + OFF_BIAS;
    float* s_wro  = sm + OFF_WRO;
    float* s_wext = sm + OFF_WEXT;
    float* s_rext = sm + OFF_REXT;

    const int b    = blockIdx.x;
    const int tid  = threadIdx.x;
    const int w    = tid >> 5;     // warp id 0..19
    const int lane = tid & 31;

    // Roles (disjoint thread sets; one unified per-thread state array `st`):
    //  W-warps : tid <  320 (warps 0..9)  -> st[0..6]=Wa, [7..13]=Wb, [14..20]=wta, [21..27]=wtb
    //  Wr-set  : 320 <= tid < 620        -> st[0..33] = Wm chunk
    //  spare   : tid >= 620              -> barriers only
    const bool is_w  = (tid < 320);
    const int  tt    = tid - 320;
    const bool is_wr = (tid >= 320) && (tt < 300);

    const float dt = timev[1] - timev[0];
    const float cW = dt * (1.0f / 5.0f);  // dt / TAU_W
    const float cR = dt;                  // dt / TAU_R

    // output section offsets
    const size_t WF   = (size_t)T_TOT * B * N_REC;
    const size_t WTF  = WF + (size_t)B * (N_MBON * N_KC);
    const size_t RO   = WTF + (size_t)B * (N_MBON * N_KC);

    // ---- stage r_kc[b] slab into smem, layout [k*61 + t] (coalesced float4) ----
    const float* rkb = r_kc + (size_t)b * (N_KC * T_TOT);
    {
        const float4* src = (const float4*)rkb;
        float4* dst = (float4*)s_rk;
        for (int i = tid; i < (N_KC * T_TOT) / 4; i += NTHREADS) dst[i] = src[i];
    }

    // ---- init small shared state ----
    if (tid < 100) {
        s_bias[tid] = bias[tid];
        float r0 = (tid < N_MBON) ? 0.0f : 0.1f;
        s_r[tid] = r0;
        s_I[tid] = 0.0f;                            // DAN slice stays 0 forever
        out[(size_t)b * N_REC + tid] = r0;          // r_all[0]
    }
    if (tid >= 100 && tid < 104) s_r[tid] = 0.0f;   // zero pad (Wr reads to 101)
    if (tid < 20)  { s_wro[tid] = W_readout[tid]; s_rbd[tid] = 0.1f; }
    if (tid < 120) s_wext[tid] = W_ext[tid];
    if (tid < 200) s_rbk[tid] = rkb[tid * T_TOT];   // rbk0 into buffer 0
    if (tid < 122) s_rext[tid] = r_ext[(size_t)b * (N_EXT * T_TOT) + tid];
    if (tid == 0)  out[RO + b] = 0.0f;              // readout0 (MBON r is 0)

    // ---- unified per-thread state ----
    float st[WM_CHUNK];
    #pragma unroll
    for (int c = 0; c < WM_CHUNK; c++) st[c] = 0.0f;

    const int m1 = w;          // W-warp row 1 (valid for w < 10)
    const int m2 = w + 10;     // W-warp row 2
    const int jj = is_wr ? (tt % 100) : 0;
    const int i0 = is_wr ? (tt / 100) * WM_CHUNK : 0;

    if (is_w) {
        const float* Wg  = W0  + (size_t)b * (N_MBON * N_KC);
        const float* wtg = wt0 + (size_t)b * (N_MBON * N_KC);
        #pragma unroll
        for (int i = 0; i < KPT; i++) {
            int k = lane + 32 * i;
            if (k < N_KC) {
                st[i]      = Wg [m1 * N_KC + k];
                st[7 + i]  = Wg [m2 * N_KC + k];
                st[14 + i] = wtg[m1 * N_KC + k];
                st[21 + i] = wtg[m2 * N_KC + k];
            }
        }
    } else if (is_wr) {
        #pragma unroll
        for (int c = 0; c < WM_CHUNK; c++) {
            int ia = i0 + c;
            float v = 0.0f;
            if (ia < N_REC) {
                v = W_recur[jj * N_REC + ia];
                if (jj < N_MBON && ia >= N_REC - N_DAN) v = 0.0f;  // Wm mask
            }
            st[c] = v;
        }
    }

    __syncthreads();

    for (int t = 0; t < T_STEPS; t++) {
        const int cur = t & 1;
        const int nxt = cur ^ 1;

        // ================= P0 (role-parallel) =================
        if (is_w) {
            // I_kc row dots (W rows m1, m2), rk streamed from smem
            float p1 = 0.0f, p2 = 0.0f;
            #pragma unroll
            for (int i = 0; i < KPT; i++) {
                int k = lane + 32 * i;
                float rk = (k < N_KC) ? s_rk[k * T_TOT + t] : 0.0f;
                p1 = fmaf(st[i],     rk, p1);
                p2 = fmaf(st[7 + i], rk, p2);
            }
            #pragma unroll
            for (int o = 16; o > 0; o >>= 1) {
                p1 += __shfl_xor_sync(0xFFFFFFFFu, p1, o);
                p2 += __shfl_xor_sync(0xFFFFFFFFu, p2, o);
            }
            if (lane == 0) { s_I[m1] = p1; s_I[m2] = p2; }

            // I_fbn (threads 0..59)
            if (tid < N_FBN) {
                float re0 = s_rext[t];
                float re1 = s_rext[T_TOT + t];
                s_I[N_MBON + tid] = fmaf(s_wext[tid * 2], re0, s_wext[tid * 2 + 1] * re1);
            }

            // rbk update (threads 0..199): read buf[cur], write buf[nxt]
            if (tid < N_KC) {
                float rbk = s_rbk[cur * 200 + tid];
                float rkt = s_rk[tid * T_TOT + t];
                s_rbk[nxt * 200 + tid] = fmaf(rkt - rbk, cW, rbk);
            }
        } else if (is_wr) {
            // Wr partials: broadcast LDS reads, 2 accumulator chains
            float a0 = 0.0f, a1 = 0.0f;
            #pragma unroll
            for (int c = 0; c < WM_CHUNK; c += 2) {
                a0 = fmaf(st[c],     s_r[i0 + c],     a0);
                a1 = fmaf(st[c + 1], s_r[i0 + c + 1], a1);
            }
            s_wrp[tt] = a0 + a1;
        }
        __syncthreads();

        // ================= P1 =================
        if (tid < N_REC) {
            float x = s_wrp[tid] + s_wrp[100 + tid] + s_wrp[200 + tid]
                    + s_bias[tid] + s_I[tid];
            float rold = s_r[tid];
            float rn = fmaf(fmaxf(x, 0.0f) - rold, cR, rold);
            s_r[tid] = rn;
            out[((size_t)(t + 1) * B + b) * N_REC + tid] = rn;
            if (tid >= N_REC - N_DAN) {
                int d = tid - (N_REC - N_DAN);
                float rbd = s_rbd[d];
                s_rbd[d] = fmaf(rn - rbd, cW, rbd);
            }
        }
        __syncthreads();

        // ================= P2 (role-parallel; rbk double-buffered, no 3rd barrier) ====
        if (is_w) {
            float rbd1 = s_rbd[m1],      rbd2 = s_rbd[m2];
            float rdn1 = -s_r[80 + m1],  rdn2 = -s_r[80 + m2];
            const float* rbk_new = s_rbk + nxt * 200;
            #pragma unroll
            for (int i = 0; i < KPT; i++) {
                int k = lane + 32 * i;
                if (k < N_KC) {
                    float rk  = s_rk[k * T_TOT + t];
                    float rbk = rbk_new[k];
                    float dw1 = fmaf(rbd1, rk, rdn1 * rbk);
                    st[14 + i] = fmaf(dw1, dt, st[14 + i]);
                    st[i] = fminf(fmaxf(fmaf(st[14 + i] - st[i], cW, st[i]), 0.0f), 0.05f);
                    float dw2 = fmaf(rbd2, rk, rdn2 * rbk);
                    st[21 + i] = fmaf(dw2, dt, st[21 + i]);
                    st[7 + i] = fminf(fmaxf(fmaf(st[21 + i] - st[7 + i], cW, st[7 + i]), 0.0f), 0.05f);
                }
            }
        } else if (w == 19) {
            // readout on a Wr-side warp (idle in P2); reads post-barrier s_r
            float v = (lane < N_MBON) ? s_r[lane] * s_wro[lane] : 0.0f;
            #pragma unroll
            for (int o = 16; o > 0; o >>= 1)
                v += __shfl_xor_sync(0xFFFFFFFFu, v, o);
            if (lane == 0) out[RO + (size_t)(t + 1) * B + b] = v;
        }
        // no trailing barrier: next P0's writers (s_I by W-warps, s_wrp by
        // Wr-set, s_rbk[cur] by W-warps) have readers >= 1 barrier away, and
        // s_r readers in next P0 see the P1 values (1 barrier away).
    }

    // ---- final W / wt ----
    if (is_w) {
        float* Wf  = out + WF  + (size_t)b * (N_MBON * N_KC);
        float* wtf = out + WTF + (size_t)b * (N_MBON * N_KC);
        #pragma unroll
        for (int i = 0; i < KPT; i++) {
            int k = lane + 32 * i;
            if (k < N_KC) {
                Wf [m1 * N_KC + k] = st[i];
                Wf [m2 * N_KC + k] = st[7 + i];
                wtf[m1 * N_KC + k] = st[14 + i];
                wtf[m2 * N_KC + k] = st[21 + i];
            }
        }
    }
}

extern "C" void kernel_launch(void* const* d_in, const int* in_sizes, int n_in,
                              void* d_out, int out_size) {
    const float* r_kc      = (const float*)d_in[0];
    const float* r_ext     = (const float*)d_in[1];
    const float* timev     = (const float*)d_in[2];
    const float* W0        = (const float*)d_in[3];
    const float* wt0       = (const float*)d_in[4];
    const float* W_recur   = (const float*)d_in[5];
    const float* W_ext     = (const float*)d_in[6];
    const float* W_readout = (const float*)d_in[7];
    const float* bias      = (const float*)d_in[8];
    float* out = (float*)d_out;

    int B = in_sizes[0] / (N_KC * T_TOT);

    static bool attr_set = false;
    if (!attr_set) {
        cudaFuncSetAttribute(cond_rnn_kernel,
                             cudaFuncAttributeMaxDynamicSharedMemorySize,
                             SM_FLOATS * sizeof(float));
        attr_set = true;
    }

    cond_rnn_kernel<<<B, NTHREADS, SM_FLOATS * sizeof(float)>>>(
        r_kc, r_ext, timev, W0, wt0, W_recur, W_ext, W_readout, bias, out, B);
}

// round 6
// speedup vs baseline: 1.0879x; 1.0196x over previous
#include <cuda_runtime.h>
#include <cstddef>

// Problem constants (fixed by reference)
#define N_KC   200
#define N_MBON 20
#define N_FBN  60
#define N_DAN  20
#define N_REC  100
#define T_TOT  61
#define T_STEPS 60
#define KPT    7          // k = lane + 32*i, valid k < 200
#define NTHREADS 640
#define WRT    500        // threads computing Wr (5 groups x 100)
#define WRC    20         // Wm cols per Wr thread
#define WRQ    5          // float4 chunks per Wr thread

// smem layout (floats)
#define OFF_RK   0        // 12200 : r_kc slab [k*61 + t]
#define OFF_R    12200    // 100   : current r
#define OFF_I    12300    // 100   : I_tot
#define OFF_WRP  12400    // 500   : Wr partials (5 groups x 100)
#define OFF_RBK  12900    // 400   : rbk double buffer (2 x 200)
#define OFF_RBD  13300    // 20
#define OFF_BIAS 13320    // 100
#define OFF_WRO  13420    // 20
#define OFF_WEXT 13440    // 120
#define OFF_REXT 13560    // 122
#define SM_FLOATS 13682

__global__ __launch_bounds__(NTHREADS, 2)
void cond_rnn_kernel(const float* __restrict__ r_kc,
                     const float* __restrict__ r_ext,
                     const float* __restrict__ timev,
                     const float* __restrict__ W0,
                     const float* __restrict__ wt0,
                     const float* __restrict__ W_recur,
                     const float* __restrict__ W_ext,
                     const float* __restrict__ W_readout,
                     const float* __restrict__ bias,
                     float* __restrict__ out,
                     int B)
{
    extern __shared__ float sm[];
    float* s_rk   = sm + OFF_RK;
    float* s_r    = sm + OFF_R;
    float* s_I    = sm + OFF_I;
    float* s_wrp  = sm + OFF_WRP;
    float* s_rbk  = sm + OFF_RBK;   // two buffers of 200
    float* s_rbd  = sm + OFF_RBD;
    float* s_bias = sm + OFF_BIAS;
    float* s_wro  = sm + OFF_WRO;
    float* s_wext = sm + OFF_WEXT;
    float* s_rext = sm + OFF_REXT;

    const int b    = blockIdx.x;
    const int tid  = threadIdx.x;
    const int w    = tid >> 5;     // warp id 0..19  == MBON row
    const int lane = tid & 31;

    const float dt = timev[1] - timev[0];
    const float cW = dt * (1.0f / 5.0f);  // dt / TAU_W
    const float cR = dt;                  // dt / TAU_R

    // output section offsets
    const size_t WF   = (size_t)T_TOT * B * N_REC;
    const size_t WTF  = WF + (size_t)B * (N_MBON * N_KC);
    const size_t RO   = WTF + (size_t)B * (N_MBON * N_KC);

    // ---- stage r_kc[b] slab into smem, natural layout [k*61 + t] ----
    const float* rkb = r_kc + (size_t)b * (N_KC * T_TOT);
    {
        const float4* src = (const float4*)rkb;
        float4* dst = (float4*)s_rk;
        for (int i = tid; i < (N_KC * T_TOT) / 4; i += NTHREADS) dst[i] = src[i];
    }

    // ---- init small shared state ----
    if (tid < 100) {
        s_bias[tid] = bias[tid];
        float r0 = (tid < N_MBON) ? 0.0f : 0.1f;
        s_r[tid] = r0;
        s_I[tid] = 0.0f;                            // DAN slice stays 0 forever
        out[(size_t)b * N_REC + tid] = r0;          // r_all[0]
    }
    if (tid < 20)  { s_wro[tid] = W_readout[tid]; s_rbd[tid] = 0.1f; }
    if (tid < 120) s_wext[tid] = W_ext[tid];
    if (tid < 200) s_rbk[tid] = rkb[tid * T_TOT];   // rbk(0) into buffer 0
    if (tid < 122) s_rext[tid] = r_ext[(size_t)b * (2 * T_TOT) + tid];
    if (tid == 0)  out[RO + b] = 0.0f;              // readout0 (MBON r is 0)

    // ---- plastic weights: warp w owns MBON row w (7 regs each) ----
    float W[KPT], wt[KPT];
    {
        const float* Wg  = W0  + (size_t)b * (N_MBON * N_KC) + w * N_KC;
        const float* wtg = wt0 + (size_t)b * (N_MBON * N_KC) + w * N_KC;
        #pragma unroll
        for (int i = 0; i < KPT; i++) {
            int k = lane + 32 * i;
            bool ok = (k < N_KC);
            W[i]  = ok ? Wg[k]  : 0.0f;
            wt[i] = ok ? wtg[k] : 0.0f;
        }
    }

    // ---- Wr weights: thread (g = tid/100, j = tid%100) owns Wm[j, 20g..20g+19] ----
    const bool is_wr = (tid < WRT);
    const int  g  = tid / 100;
    const int  j  = tid - g * 100;
    const int  c0 = g * WRC;
    float wm[WRC];
    #pragma unroll
    for (int c = 0; c < WRC; c++) {
        int i = c0 + c;
        float v = 0.0f;
        if (is_wr) {
            v = W_recur[j * N_REC + i];
            if (j < N_MBON && i >= N_REC - N_DAN) v = 0.0f;   // Wm mask
        }
        wm[c] = v;
    }

    __syncthreads();

    for (int t = 0; t < T_STEPS; t++) {
        const int cur = t & 1;          // rbk(t) lives in buf[cur]
        const int nxt = cur ^ 1;

        // =============== BIGPHASE: P2(t-1) + P0(t), all warps busy ===============

        // --- P2(t-1): plasticity for row w (uses rk(t-1), rbk(t), rbd(t), r_dan(t)) ---
        if (t > 0) {
            float rbd_w = s_rbd[w];
            float rdn   = -s_r[80 + w];
            const float* rbk_t = s_rbk + cur * 200;
            #pragma unroll
            for (int i = 0; i < KPT; i++) {
                int k = lane + 32 * i;
                if (k < N_KC) {
                    float rkp = s_rk[k * T_TOT + (t - 1)];
                    float rbk = rbk_t[k];
                    float dw  = fmaf(rbd_w, rkp, rdn * rbk);
                    wt[i] = fmaf(dw, dt, wt[i]);
                    W[i]  = fminf(fmaxf(fmaf(wt[i] - W[i], cW, W[i]), 0.0f), 0.05f);
                }
            }
        }

        // --- I_kc(t): row-w dot, shuffle reduce ---
        {
            float p = 0.0f;
            #pragma unroll
            for (int i = 0; i < KPT; i++) {
                int k = lane + 32 * i;
                float rk = (k < N_KC) ? s_rk[k * T_TOT + t] : 0.0f;
                p = fmaf(W[i], rk, p);
            }
            #pragma unroll
            for (int o = 16; o > 0; o >>= 1)
                p += __shfl_xor_sync(0xFFFFFFFFu, p, o);
            if (lane == 0) s_I[w] = p;
        }

        // --- Wr(t): 5-way split GEMV partials (threads 0..499) ---
        if (is_wr) {
            float a0 = 0.0f, a1 = 0.0f;
            #pragma unroll
            for (int c = 0; c < WRQ; c++) {
                float4 rv = *(const float4*)(s_r + c0 + 4 * c);
                a0 = fmaf(wm[4 * c],     rv.x, a0);
                a1 = fmaf(wm[4 * c + 1], rv.y, a1);
                a0 = fmaf(wm[4 * c + 2], rv.z, a0);
                a1 = fmaf(wm[4 * c + 3], rv.w, a1);
            }
            s_wrp[tid] = a0 + a1;                     // [g*100 + j]
        } else if (w == 16 || w == 17) {
            // --- I_fbn(t): threads 512..571 ---
            int q = tid - 512;
            if (q < N_FBN) {
                float re0 = s_rext[t];
                float re1 = s_rext[T_TOT + t];
                s_I[N_MBON + q] = fmaf(s_wext[2 * q], re0, s_wext[2 * q + 1] * re1);
            }
        } else if (w == 18) {
            // --- rbk update: rbk(t+1) = lerp(rbk(t), rk(t)); buf[cur] -> buf[nxt] ---
            #pragma unroll
            for (int q = 0; q < 224; q += 32) {
                int k = q + lane;
                if (k < N_KC) {
                    float rbk = s_rbk[cur * 200 + k];
                    float rkt = s_rk[k * T_TOT + t];
                    s_rbk[nxt * 200 + k] = fmaf(rkt - rbk, cW, rbk);
                }
            }
        } else if (w == 19) {
            // --- readout(t) from current s_r = r(t) (index t; t=0 done at init) ---
            float v = (lane < N_MBON) ? s_r[lane] * s_wro[lane] : 0.0f;
            #pragma unroll
            for (int o = 16; o > 0; o >>= 1)
                v += __shfl_xor_sync(0xFFFFFFFFu, v, o);
            if (lane == 0 && t > 0) out[RO + (size_t)t * B + b] = v;
        }
        __syncthreads();

        // =============== P1: neuron update (threads 0..99) ===============
        if (tid < N_REC) {
            float x = s_wrp[tid] + s_wrp[100 + tid] + s_wrp[200 + tid]
                    + s_wrp[300 + tid] + s_wrp[400 + tid]
                    + s_bias[tid] + s_I[tid];
            float rold = s_r[tid];
            float rn = fmaf(fmaxf(x, 0.0f) - rold, cR, rold);
            s_r[tid] = rn;
            out[((size_t)(t + 1) * B + b) * N_REC + tid] = rn;
            if (tid >= N_REC - N_DAN) {
                int d = tid - (N_REC - N_DAN);
                float rbd = s_rbd[d];
                s_rbd[d] = fmaf(rn - rbd, cW, rbd);
            }
        }
        __syncthreads();
    }

    // =============== tail: P2(59), readout(60), final W/wt ===============
    {
        const int cur = T_STEPS & 1;    // rbk(60) buffer
        float rbd_w = s_rbd[w];
        float rdn   = -s_r[80 + w];
        const float* rbk_t = s_rbk + cur * 200;
        #pragma unroll
        for (int i = 0; i < KPT; i++) {
            int k = lane + 32 * i;
            if (k < N_KC) {
                float rkp = s_rk[k * T_TOT + (T_STEPS - 1)];
                float rbk = rbk_t[k];
                float dw  = fmaf(rbd_w, rkp, rdn * rbk);
                wt[i] = fmaf(dw, dt, wt[i]);
                W[i]  = fminf(fmaxf(fmaf(wt[i] - W[i], cW, W[i]), 0.0f), 0.05f);
            }
        }
        if (w == 19) {
            float v = (lane < N_MBON) ? s_r[lane] * s_wro[lane] : 0.0f;
            #pragma unroll
            for (int o = 16; o > 0; o >>= 1)
                v += __shfl_xor_sync(0xFFFFFFFFu, v, o);
            if (lane == 0) out[RO + (size_t)T_STEPS * B + b] = v;
        }
        float* Wf  = out + WF  + (size_t)b * (N_MBON * N_KC) + w * N_KC;
        float* wtf = out + WTF + (size_t)b * (N_MBON * N_KC) + w * N_KC;
        #pragma unroll
        for (int i = 0; i < KPT; i++) {
            int k = lane + 32 * i;
            if (k < N_KC) {
                Wf [k] = W[i];
                wtf[k] = wt[i];
            }
        }
    }
}

extern "C" void kernel_launch(void* const* d_in, const int* in_sizes, int n_in,
                              void* d_out, int out_size) {
    const float* r_kc      = (const float*)d_in[0];
    const float* r_ext     = (const float*)d_in[1];
    const float* timev     = (const float*)d_in[2];
    const float* W0        = (const float*)d_in[3];
    const float* wt0       = (const float*)d_in[4];
    const float* W_recur   = (const float*)d_in[5];
    const float* W_ext     = (const float*)d_in[6];
    const float* W_readout = (const float*)d_in[7];
    const float* bias      = (const float*)d_in[8];
    float* out = (float*)d_out;

    int B = in_sizes[0] / (N_KC * T_TOT);

    static bool attr_set = false;
    if (!attr_set) {
        cudaFuncSetAttribute(cond_rnn_kernel,
                             cudaFuncAttributeMaxDynamicSharedMemorySize,
                             SM_FLOATS * sizeof(float));
        attr_set = true;
    }

    cond_rnn_kernel<<<B, NTHREADS, SM_FLOATS * sizeof(float)>>>(
        r_kc, r_ext, timev, W0, wt0, W_recur, W_ext, W_readout, bias, out, B);
}

// round 7
// speedup vs baseline: 1.2613x; 1.1594x over previous
#include <cuda_runtime.h>
#include <cstddef>

// Problem constants (fixed by reference)
#define N_KC   200
#define N_MBON 20
#define N_FBN  60
#define N_DAN  20
#define N_REC  100
#define T_TOT  61
#define T_STEPS 60
#define KPT    7          // k = lane + 32*i, valid k < 200
#define NTHREADS 320
#define WM_CHUNK 34       // Wm cols per thread-group (3 groups of 100 threads)
#define WM_PAIRS 17

// smem layout (floats)
#define OFF_RK   0        // 12200 : r_kc slab [k*61 + t]
#define OFF_R    12200    // 104   : current r, zero-padded to 104 (float2 reads)
#define OFF_I    12304    // 100   : I_tot (lane-0 I_kc partial + I_fbn + zeros)
#define OFF_IB   12404    // 60    : I_kc partials from lanes 1..3 (3 x 20)
#define OFF_WRP  12464    // 300   : Wr partials
#define OFF_RBK  12764    // 400   : rbk double buffer (2 x 200)
#define OFF_RBD  13164    // 20
#define OFF_BIAS 13184    // 100
#define OFF_WRO  13284    // 20
#define OFF_WEXT 13304    // 120
#define OFF_REXT 13424    // 122
#define SM_FLOATS 13546

__global__ __launch_bounds__(NTHREADS, 2)
void cond_rnn_kernel(const float* __restrict__ r_kc,
                     const float* __restrict__ r_ext,
                     const float* __restrict__ timev,
                     const float* __restrict__ W0,
                     const float* __restrict__ wt0,
                     const float* __restrict__ W_recur,
                     const float* __restrict__ W_ext,
                     const float* __restrict__ W_readout,
                     const float* __restrict__ bias,
                     float* __restrict__ out,
                     int B)
{
    extern __shared__ float sm[];
    float* s_rk   = sm + OFF_RK;
    float* s_r    = sm + OFF_R;
    float* s_I    = sm + OFF_I;
    float* s_Ib   = sm + OFF_IB;
    float* s_wrp  = sm + OFF_WRP;
    float* s_rbk  = sm + OFF_RBK;   // two buffers of 200
    float* s_rbd  = sm + OFF_RBD;
    float* s_bias = sm + OFF_BIAS;
    float* s_wro  = sm + OFF_WRO;
    float* s_wext = sm + OFF_WEXT;
    float* s_rext = sm + OFF_REXT;

    const int b    = blockIdx.x;
    const int tid  = threadIdx.x;
    const int w    = tid >> 5;     // warp id 0..9
    const int lane = tid & 31;

    const float dt = timev[1] - timev[0];
    const float cW = dt * (1.0f / 5.0f);  // dt / TAU_W
    const float cR = dt;                  // dt / TAU_R

    // output section offsets
    const size_t WF   = (size_t)T_TOT * B * N_REC;
    const size_t WTF  = WF + (size_t)B * (N_MBON * N_KC);
    const size_t RO   = WTF + (size_t)B * (N_MBON * N_KC);

    // ---- stage r_kc[b] slab into smem (coalesced float4) ----
    const float* rkb = r_kc + (size_t)b * (N_KC * T_TOT);
    {
        const float4* src = (const float4*)rkb;
        float4* dst = (float4*)s_rk;
        for (int i = tid; i < (N_KC * T_TOT) / 4; i += NTHREADS) dst[i] = src[i];
    }

    // ---- init small shared state ----
    if (tid < 100) {
        s_bias[tid] = bias[tid];
        float r0 = (tid < N_MBON) ? 0.0f : 0.1f;
        s_r[tid] = r0;
        s_I[tid] = 0.0f;                            // DAN slice stays 0 forever
        out[(size_t)b * N_REC + tid] = r0;          // r_all[0]
    }
    if (tid >= 100 && tid < 104) s_r[tid] = 0.0f;   // zero pad for float2 Wr reads
    if (tid < 20)  { s_wro[tid] = W_readout[tid]; s_rbd[tid] = 0.1f; }
    if (tid < 120) s_wext[tid] = W_ext[tid];
    if (tid < 200) s_rbk[tid] = rkb[tid * T_TOT];   // rbk0 into buffer 0
    if (tid < 122) s_rext[tid] = r_ext[(size_t)b * (2 * T_TOT) + tid];
    if (tid == 0)  out[RO + b] = 0.0f;              // readout0 (MBON r is 0)

    // ---- plastic weights W / wt in registers: warp w owns rows (w, w+10) ----
    const int m1 = w;
    const int m2 = w + 10;
    float Wa[KPT], Wb_[KPT], wta[KPT], wtb[KPT];
    {
        const float* Wg  = W0  + (size_t)b * (N_MBON * N_KC);
        const float* wtg = wt0 + (size_t)b * (N_MBON * N_KC);
        #pragma unroll
        for (int i = 0; i < KPT; i++) {
            int k = lane + 32 * i;
            bool ok = (k < N_KC);
            Wa[i]  = ok ? Wg [m1 * N_KC + k] : 0.0f;
            Wb_[i] = ok ? Wg [m2 * N_KC + k] : 0.0f;
            wta[i] = ok ? wtg[m1 * N_KC + k] : 0.0f;
            wtb[i] = ok ? wtg[m2 * N_KC + k] : 0.0f;
        }
    }

    // ---- W_recur (masked -> Wm) in registers: thread-group (jj, i0) ----
    float wm[WM_CHUNK];
    const int jj = (tid < 300) ? (tid % 100) : 0;
    const int i0 = (tid < 300) ? (tid / 100) * WM_CHUNK : 0;
    #pragma unroll
    for (int c = 0; c < WM_CHUNK; c++) {
        int ia = i0 + c;
        float v = 0.0f;
        if (tid < 300 && ia < N_REC) {
            v = W_recur[jj * N_REC + ia];
            if (jj < N_MBON && ia >= N_REC - N_DAN) v = 0.0f;  // Wm mask
        }
        wm[c] = v;
    }

    __syncthreads();

    for (int t = 0; t < T_STEPS; t++) {
        const int cur = t & 1;
        const int nxt = cur ^ 1;

        // ================= P0 =================
        // rk into regs + I_kc row dots (2 independent chains)
        float rk[KPT];
        #pragma unroll
        for (int i = 0; i < KPT; i++) {
            int k = lane + 32 * i;
            rk[i] = (k < N_KC) ? s_rk[k * T_TOT + t] : 0.0f;
        }
        float p1 = 0.0f, p2 = 0.0f;
        #pragma unroll
        for (int i = 0; i < KPT; i++) {
            p1 = fmaf(Wa[i],  rk[i], p1);
            p2 = fmaf(Wb_[i], rk[i], p2);
        }
        // 3-level butterfly: lanes 0..3 end with partials over lanes == l mod 4
        #pragma unroll
        for (int o = 16; o >= 4; o >>= 1) {
            p1 += __shfl_xor_sync(0xFFFFFFFFu, p1, o);
            p2 += __shfl_xor_sync(0xFFFFFFFFu, p2, o);
        }
        if (lane < 4) {
            float* dst = (lane == 0) ? s_I : (s_Ib + (lane - 1) * 20);
            dst[m1] = p1;
            dst[m2] = p2;
        }

        // I_fbn
        if (tid < N_FBN) {
            float re0 = s_rext[t];
            float re1 = s_rext[T_TOT + t];
            s_I[N_MBON + tid] = fmaf(s_wext[tid * 2], re0, s_wext[tid * 2 + 1] * re1);
        }

        // Wr partials: 17 float2 broadcast loads, 4 accumulator chains
        if (tid < 300) {
            const float2* rp = (const float2*)(s_r + i0);
            float a0 = 0.f, a1 = 0.f, a2 = 0.f, a3 = 0.f;
            #pragma unroll
            for (int c = 0; c < WM_PAIRS; c++) {
                float2 rv = rp[c];
                if (c & 1) {
                    a2 = fmaf(wm[2 * c],     rv.x, a2);
                    a3 = fmaf(wm[2 * c + 1], rv.y, a3);
                } else {
                    a0 = fmaf(wm[2 * c],     rv.x, a0);
                    a1 = fmaf(wm[2 * c + 1], rv.y, a1);
                }
            }
            s_wrp[tid] = (a0 + a1) + (a2 + a3);
        }

        // rbk update: read buf[cur], write buf[nxt]
        if (tid < N_KC) {
            float rbk = s_rbk[cur * 200 + tid];
            float rkt = s_rk[tid * T_TOT + t];
            s_rbk[nxt * 200 + tid] = fmaf(rkt - rbk, cW, rbk);
        }
        __syncthreads();

        // ================= P1 =================
        if (tid < N_REC) {
            float x = s_wrp[tid] + s_wrp[100 + tid] + s_wrp[200 + tid]
                    + s_bias[tid] + s_I[tid];
            if (tid < N_MBON)
                x += s_Ib[tid] + s_Ib[20 + tid] + s_Ib[40 + tid];
            float rold = s_r[tid];
            float rn = fmaf(fmaxf(x, 0.0f) - rold, cR, rold);
            s_r[tid] = rn;
            out[((size_t)(t + 1) * B + b) * N_REC + tid] = rn;
            if (tid >= N_REC - N_DAN) {
                int d = tid - (N_REC - N_DAN);
                float rbd = s_rbd[d];
                s_rbd[d] = fmaf(rn - rbd, cW, rbd);
            }
        }
        __syncthreads();

        // ================= P2 (no trailing barrier; rbk double-buffered) ====
        {
            float rbd1d = s_rbd[m1] * dt,      rbd2d = s_rbd[m2] * dt;
            float rdn1d = -s_r[80 + m1] * dt,  rdn2d = -s_r[80 + m2] * dt;
            const float* rbk_new = s_rbk + nxt * 200;
            #pragma unroll
            for (int i = 0; i < KPT; i++) {
                int k = lane + 32 * i;
                if (k < N_KC) {
                    float rbk = rbk_new[k];
                    wta[i] = fmaf(rbd1d, rk[i], wta[i]);
                    wta[i] = fmaf(rdn1d, rbk,   wta[i]);
                    Wa[i]  = fminf(fmaxf(fmaf(wta[i] - Wa[i], cW, Wa[i]), 0.0f), 0.05f);
                    wtb[i] = fmaf(rbd2d, rk[i], wtb[i]);
                    wtb[i] = fmaf(rdn2d, rbk,   wtb[i]);
                    Wb_[i] = fminf(fmaxf(fmaf(wtb[i] - Wb_[i], cW, Wb_[i]), 0.0f), 0.05f);
                }
            }
        }

        // readout (warp 0; reads post-barrier s_r)
        if (w == 0) {
            float v = (lane < N_MBON) ? s_r[lane] * s_wro[lane] : 0.0f;
            #pragma unroll
            for (int o = 16; o > 0; o >>= 1)
                v += __shfl_xor_sync(0xFFFFFFFFu, v, o);
            if (lane == 0) out[RO + (size_t)(t + 1) * B + b] = v;
        }
        // no trailing barrier: next P0 writes s_I/s_Ib/s_wrp (their readers in
        // P1 are 1 barrier ahead; P2/readout don't touch them) and rbk
        // buf[cur] (last read by P0(t), 2 barriers back).
    }

    // ---- final W / wt ----
    {
        float* Wf  = out + WF  + (size_t)b * (N_MBON * N_KC);
        float* wtf = out + WTF + (size_t)b * (N_MBON * N_KC);
        #pragma unroll
        for (int i = 0; i < KPT; i++) {
            int k = lane + 32 * i;
            if (k < N_KC) {
                Wf [m1 * N_KC + k] = Wa[i];
                Wf [m2 * N_KC + k] = Wb_[i];
                wtf[m1 * N_KC + k] = wta[i];
                wtf[m2 * N_KC + k] = wtb[i];
            }
        }
    }
}

extern "C" void kernel_launch(void* const* d_in, const int* in_sizes, int n_in,
                              void* d_out, int out_size) {
    const float* r_kc      = (const float*)d_in[0];
    const float* r_ext     = (const float*)d_in[1];
    const float* timev     = (const float*)d_in[2];
    const float* W0        = (const float*)d_in[3];
    const float* wt0       = (const float*)d_in[4];
    const float* W_recur   = (const float*)d_in[5];
    const float* W_ext     = (const float*)d_in[6];
    const float* W_readout = (const float*)d_in[7];
    const float* bias      = (const float*)d_in[8];
    float* out = (float*)d_out;

    int B = in_sizes[0] / (N_KC * T_TOT);

    static bool attr_set = false;
    if (!attr_set) {
        cudaFuncSetAttribute(cond_rnn_kernel,
                             cudaFuncAttributeMaxDynamicSharedMemorySize,
                             SM_FLOATS * sizeof(float));
        attr_set = true;
    }

    cond_rnn_kernel<<<B, NTHREADS, SM_FLOATS * sizeof(float)>>>(
        r_kc, r_ext, timev, W0, wt0, W_recur, W_ext, W_readout, bias, out, B);
}

// round 8
// speedup vs baseline: 1.3183x; 1.0452x over previous
#include <cuda_runtime.h>
#include <cstddef>

// Problem constants (fixed by reference)
#define N_KC   200
#define N_MBON 20
#define N_FBN  60
#define N_DAN  20
#define N_REC  100
#define T_TOT  61
#define T_STEPS 60
#define KPT    7          // k = lane + 32*i, valid k < 200
#define NTHREADS 320
#define WM_CHUNK 36       // Wm cols per thread-group (9 float4s, zero-padded)
#define WM_Q     9

// smem layout (floats)
#define OFF_RK   0        // 12200 : r_kc slab [k*61 + t]
#define OFF_R    12200    // 108   : current r, zero-padded to 108 (float4 reads)
#define OFF_IB   12308    // 80    : I_kc partials (4 lanes x 20 rows)
#define OFF_WRP  12388    // 300   : Wr partials
#define OFF_RBK  12688    // 400   : rbk double buffer (2 x 200)
#define OFF_RBD  13088    // 20
#define OFF_BIAS 13108    // 100
#define OFF_WRO  13208    // 20
#define OFF_WEXT 13228    // 120
#define OFF_REXT 13348    // 122
#define SM_FLOATS 13470

__global__ __launch_bounds__(NTHREADS, 2)
void cond_rnn_kernel(const float* __restrict__ r_kc,
                     const float* __restrict__ r_ext,
                     const float* __restrict__ timev,
                     const float* __restrict__ W0,
                     const float* __restrict__ wt0,
                     const float* __restrict__ W_recur,
                     const float* __restrict__ W_ext,
                     const float* __restrict__ W_readout,
                     const float* __restrict__ bias,
                     float* __restrict__ out,
                     int B)
{
    extern __shared__ float sm[];
    float* s_rk   = sm + OFF_RK;
    float* s_r    = sm + OFF_R;
    float* s_Ib   = sm + OFF_IB;
    float* s_wrp  = sm + OFF_WRP;
    float* s_rbk  = sm + OFF_RBK;   // two buffers of 200
    float* s_rbd  = sm + OFF_RBD;
    float* s_bias = sm + OFF_BIAS;
    float* s_wro  = sm + OFF_WRO;
    float* s_wext = sm + OFF_WEXT;
    float* s_rext = sm + OFF_REXT;

    const int b    = blockIdx.x;
    const int tid  = threadIdx.x;
    const int w    = tid >> 5;     // warp id 0..9
    const int lane = tid & 31;

    const float dt = timev[1] - timev[0];
    const float cW = dt * (1.0f / 5.0f);  // dt / TAU_W
    const float cR = dt;                  // dt / TAU_R

    // output section offsets
    const size_t WF   = (size_t)T_TOT * B * N_REC;
    const size_t WTF  = WF + (size_t)B * (N_MBON * N_KC);
    const size_t RO   = WTF + (size_t)B * (N_MBON * N_KC);

    // ---- stage r_kc[b] slab into smem (coalesced float4) ----
    const float* rkb = r_kc + (size_t)b * (N_KC * T_TOT);
    {
        const float4* src = (const float4*)rkb;
        float4* dst = (float4*)s_rk;
        for (int i = tid; i < (N_KC * T_TOT) / 4; i += NTHREADS) dst[i] = src[i];
    }

    // ---- init small shared state ----
    if (tid < 100) {
        s_bias[tid] = bias[tid];
        float r0 = (tid < N_MBON) ? 0.0f : 0.1f;
        s_r[tid] = r0;
        out[(size_t)b * N_REC + tid] = r0;          // r_all[0]
    }
    if (tid >= 100 && tid < 108) s_r[tid] = 0.0f;   // zero pad for float4 Wr reads
    if (tid < 20)  { s_wro[tid] = W_readout[tid]; s_rbd[tid] = 0.1f; }
    if (tid < 120) s_wext[tid] = W_ext[tid];
    if (tid < 200) s_rbk[tid] = rkb[tid * T_TOT];   // rbk0 into buffer 0
    if (tid < 122) s_rext[tid] = r_ext[(size_t)b * (2 * T_TOT) + tid];
    if (tid == 0)  out[RO + b] = 0.0f;              // readout0 (MBON r is 0)

    // ---- plastic weights W / wt in registers: warp w owns rows (w, w+10) ----
    const int m1 = w;
    const int m2 = w + 10;
    float Wa[KPT], Wb_[KPT], wta[KPT], wtb[KPT];
    {
        const float* Wg  = W0  + (size_t)b * (N_MBON * N_KC);
        const float* wtg = wt0 + (size_t)b * (N_MBON * N_KC);
        #pragma unroll
        for (int i = 0; i < KPT; i++) {
            int k = lane + 32 * i;
            bool ok = (k < N_KC);
            Wa[i]  = ok ? Wg [m1 * N_KC + k] : 0.0f;
            Wb_[i] = ok ? Wg [m2 * N_KC + k] : 0.0f;
            wta[i] = ok ? wtg[m1 * N_KC + k] : 0.0f;
            wtb[i] = ok ? wtg[m2 * N_KC + k] : 0.0f;
        }
    }

    // ---- W_recur (masked -> Wm) in registers: thread-group (jj, i0) ----
    float wm[WM_CHUNK];
    const int jj = (tid < 300) ? (tid % 100) : 0;
    const int i0 = (tid < 300) ? (tid / 100) * WM_CHUNK : 0;
    #pragma unroll
    for (int c = 0; c < WM_CHUNK; c++) {
        int ia = i0 + c;
        float v = 0.0f;
        if (tid < 300 && ia < N_REC) {
            v = W_recur[jj * N_REC + ia];
            if (jj < N_MBON && ia >= N_REC - N_DAN) v = 0.0f;  // Wm mask
        }
        wm[c] = v;
    }

    __syncthreads();

    for (int t = 0; t < T_STEPS; t++) {
        const int cur = t & 1;
        const int nxt = cur ^ 1;

        // ================= P0 =================
        // rk into regs + I_kc row dots (2 independent chains)
        float rk[KPT];
        #pragma unroll
        for (int i = 0; i < KPT; i++) {
            int k = lane + 32 * i;
            rk[i] = (k < N_KC) ? s_rk[k * T_TOT + t] : 0.0f;
        }
        float p1 = 0.0f, p2 = 0.0f;
        #pragma unroll
        for (int i = 0; i < KPT; i++) {
            p1 = fmaf(Wa[i],  rk[i], p1);
            p2 = fmaf(Wb_[i], rk[i], p2);
        }
        // 3-level butterfly: lanes 0..3 hold partials over lanes == l mod 4
        #pragma unroll
        for (int o = 16; o >= 4; o >>= 1) {
            p1 += __shfl_xor_sync(0xFFFFFFFFu, p1, o);
            p2 += __shfl_xor_sync(0xFFFFFFFFu, p2, o);
        }
        if (lane < 4) {
            s_Ib[lane * 20 + m1] = p1;
            s_Ib[lane * 20 + m2] = p2;
        }

        // Wr partials: 9 float4 broadcast loads, 2 accumulator chains
        if (tid < 300) {
            const float4* rp = (const float4*)(s_r + i0);
            float a0 = 0.f, a1 = 0.f;
            #pragma unroll
            for (int c = 0; c < WM_Q; c++) {
                float4 rv = rp[c];
                a0 = fmaf(wm[4 * c],     rv.x, a0);
                a1 = fmaf(wm[4 * c + 1], rv.y, a1);
                a0 = fmaf(wm[4 * c + 2], rv.z, a0);
                a1 = fmaf(wm[4 * c + 3], rv.w, a1);
            }
            s_wrp[tid] = a0 + a1;
        }

        // rbk update: read buf[cur], write buf[nxt]
        if (tid < N_KC) {
            float rbk = s_rbk[cur * 200 + tid];
            float rkt = s_rk[tid * T_TOT + t];
            s_rbk[nxt * 200 + tid] = fmaf(rkt - rbk, cW, rbk);
        }
        __syncthreads();

        // ================= P1 (I_fbn folded in) =================
        if (tid < N_REC) {
            float x = s_wrp[tid] + s_wrp[100 + tid] + s_wrp[200 + tid]
                    + s_bias[tid];
            if (tid < N_MBON) {
                x += (s_Ib[tid] + s_Ib[20 + tid]) + (s_Ib[40 + tid] + s_Ib[60 + tid]);
            } else if (tid < N_MBON + N_FBN) {
                int q = tid - N_MBON;
                float re0 = s_rext[t];
                float re1 = s_rext[T_TOT + t];
                x += fmaf(s_wext[2 * q], re0, s_wext[2 * q + 1] * re1);
            }
            float rold = s_r[tid];
            float rn = fmaf(fmaxf(x, 0.0f) - rold, cR, rold);
            s_r[tid] = rn;
            out[((size_t)(t + 1) * B + b) * N_REC + tid] = rn;
            if (tid >= N_REC - N_DAN) {
                int d = tid - (N_REC - N_DAN);
                float rbd = s_rbd[d];
                s_rbd[d] = fmaf(rn - rbd, cW, rbd);
            }
        }
        __syncthreads();

        // ================= P2 (no trailing barrier; rbk double-buffered) ====
        {
            float rbd1d = s_rbd[m1] * dt,      rbd2d = s_rbd[m2] * dt;
            float rdn1d = -s_r[80 + m1] * dt,  rdn2d = -s_r[80 + m2] * dt;
            const float* rbk_new = s_rbk + nxt * 200;
            #pragma unroll
            for (int i = 0; i < KPT; i++) {
                int k = lane + 32 * i;
                if (k < N_KC) {
                    float rbk = rbk_new[k];
                    wta[i] = fmaf(rbd1d, rk[i], wta[i]);
                    wta[i] = fmaf(rdn1d, rbk,   wta[i]);
                    Wa[i]  = fminf(fmaxf(fmaf(wta[i] - Wa[i], cW, Wa[i]), 0.0f), 0.05f);
                    wtb[i] = fmaf(rbd2d, rk[i], wtb[i]);
                    wtb[i] = fmaf(rdn2d, rbk,   wtb[i]);
                    Wb_[i] = fminf(fmaxf(fmaf(wtb[i] - Wb_[i], cW, Wb_[i]), 0.0f), 0.05f);
                }
            }
        }

        // readout (warp 9, lightest-loaded; reads post-barrier s_r)
        if (w == 9) {
            float v = (lane < N_MBON) ? s_r[lane] * s_wro[lane] : 0.0f;
            #pragma unroll
            for (int o = 16; o > 0; o >>= 1)
                v += __shfl_xor_sync(0xFFFFFFFFu, v, o);
            if (lane == 0) out[RO + (size_t)(t + 1) * B + b] = v;
        }
        // no trailing barrier: next P0 writes s_Ib/s_wrp (readers in P1 are 1
        // barrier ahead; P2/readout don't touch them) and rbk buf[cur] (last
        // read by P0(t), 2 barriers back).
    }

    // ---- final W / wt ----
    {
        float* Wf  = out + WF  + (size_t)b * (N_MBON * N_KC);
        float* wtf = out + WTF + (size_t)b * (N_MBON * N_KC);
        #pragma unroll
        for (int i = 0; i < KPT; i++) {
            int k = lane + 32 * i;
            if (k < N_KC) {
                Wf [m1 * N_KC + k] = Wa[i];
                Wf [m2 * N_KC + k] = Wb_[i];
                wtf[m1 * N_KC + k] = wta[i];
                wtf[m2 * N_KC + k] = wtb[i];
            }
        }
    }
}

extern "C" void kernel_launch(void* const* d_in, const int* in_sizes, int n_in,
                              void* d_out, int out_size) {
    const float* r_kc      = (const float*)d_in[0];
    const float* r_ext     = (const float*)d_in[1];
    const float* timev     = (const float*)d_in[2];
    const float* W0        = (const float*)d_in[3];
    const float* wt0       = (const float*)d_in[4];
    const float* W_recur   = (const float*)d_in[5];
    const float* W_ext     = (const float*)d_in[6];
    const float* W_readout = (const float*)d_in[7];
    const float* bias      = (const float*)d_in[8];
    float* out = (float*)d_out;

    int B = in_sizes[0] / (N_KC * T_TOT);

    static bool attr_set = false;
    if (!attr_set) {
        cudaFuncSetAttribute(cond_rnn_kernel,
                             cudaFuncAttributeMaxDynamicSharedMemorySize,
                             SM_FLOATS * sizeof(float));
        attr_set = true;
    }

    cond_rnn_kernel<<<B, NTHREADS, SM_FLOATS * sizeof(float)>>>(
        r_kc, r_ext, timev, W0, wt0, W_recur, W_ext, W_readout, bias, out, B);
}